// round 3
// baseline (speedup 1.0000x reference)
#include <cuda_runtime.h>
#include <math.h>

#define B_ 16384
#define S_ 32
#define D_ 64
#define KTOP 3

constexpr int SD = S_ * D_;                      // 2048 floats per mem row
constexpr long long OFF_READ_R = 0;
constexpr long long OFF_READ_I = (long long)B_ * D_;                 // 1,048,576
constexpr long long OFF_NEXT_R = 2LL * B_ * D_;                      // 2,097,152
constexpr long long OFF_NEXT_I = OFF_NEXT_R + (long long)B_ * SD;    // 35,651,584
constexpr long long OFF_ENT    = OFF_NEXT_I + (long long)B_ * SD;    // 69,206,016

__global__ void am_init_kernel(float* __restrict__ out) {
    out[OFF_ENT] = 0.0f;
}

__global__ __launch_bounds__(256) void am_fused_kernel(
    const float* __restrict__ gw_r,  const float* __restrict__ gw_i,
    const float* __restrict__ mem_r, const float* __restrict__ mem_i,
    const float* __restrict__ Wg,    const float* __restrict__ bg,
    const float* __restrict__ Wa,    const float* __restrict__ ba,
    const float* __restrict__ gamma_r, const float* __restrict__ beta_r,
    const float* __restrict__ gamma_i, const float* __restrict__ beta_i,
    float* __restrict__ out)
{
    __shared__ float smr[SD];
    __shared__ float smi[SD];
    __shared__ float gwr[D_], gwi[D_];
    __shared__ float gr[D_], br[D_], gi[D_], bi[D_];
    __shared__ float sim[S_], logi[S_], attn[S_], sparse[S_];
    __shared__ float s_wg;

    const int t = threadIdx.x;
    const int b = blockIdx.x;
    const long long baseSD = (long long)b * SD;

    // ---- Stage prev_mem row into SMEM (fully coalesced float4) ----
    {
        const float4* gmr4 = (const float4*)(mem_r + baseSD);
        const float4* gmi4 = (const float4*)(mem_i + baseSD);
        float4* sr4 = (float4*)smr;
        float4* si4 = (float4*)smi;
        sr4[t]       = gmr4[t];
        sr4[t + 256] = gmr4[t + 256];
        si4[t]       = gmi4[t];
        si4[t + 256] = gmi4[t + 256];
    }
    // ---- Small per-row / constant vectors ----
    if (t < 64) {
        gwr[t] = gw_r[(long long)b * D_ + t];
        gr[t]  = gamma_r[t];
    } else if (t < 128) {
        const int d = t - 64;
        gwi[d] = gw_i[(long long)b * D_ + d];
        br[d]  = beta_r[d];
    } else if (t < 192) {
        gi[t - 128] = gamma_i[t - 128];
    } else {
        bi[t - 192] = beta_i[t - 192];
    }
    __syncthreads();

    // ---- sim[s] and logits[s] partials: 8 threads per s-row ----
    {
        const int s   = t >> 3;
        const int sub = t & 7;
        const int d0  = sub * 8;
        float acc = 0.0f;
        #pragma unroll
        for (int i = 0; i < 8; i++) {
            const int d = d0 + i;
            acc = fmaf(smr[s * D_ + d], gwr[d], acc);
            acc = fmaf(smi[s * D_ + d], gwi[d], acc);
        }
        acc += __shfl_xor_sync(0xffffffffu, acc, 4);
        acc += __shfl_xor_sync(0xffffffffu, acc, 2);
        acc += __shfl_xor_sync(0xffffffffu, acc, 1);
        if (sub == 0) sim[s] = acc;

        // logits: flat = [gw_r, gw_i] (128), each sub handles 16 j's
        float lacc = 0.0f;
        const int j0 = sub * 16;
        #pragma unroll
        for (int i = 0; i < 16; i++) {
            const int j = j0 + i;
            const float f = (j < 64) ? gwr[j] : gwi[j - 64];
            lacc = fmaf(f, Wa[j * S_ + s], lacc);
        }
        lacc += __shfl_xor_sync(0xffffffffu, lacc, 4);
        lacc += __shfl_xor_sync(0xffffffffu, lacc, 2);
        lacc += __shfl_xor_sync(0xffffffffu, lacc, 1);
        if (sub == 0) logi[s] = lacc + ba[s];
    }
    __syncthreads();

    const int warp = t >> 5;
    const int lane = t & 31;

    if (warp == 0) {
        // ---- attention softmax over S=32 (one lane per slot) ----
        const float v = sim[lane];
        float m = v;
        #pragma unroll
        for (int o = 16; o; o >>= 1) m = fmaxf(m, __shfl_xor_sync(0xffffffffu, m, o));
        const float e = __expf(v - m);
        float ssum = e;
        #pragma unroll
        for (int o = 16; o; o >>= 1) ssum += __shfl_xor_sync(0xffffffffu, ssum, o);
        attn[lane] = e / ssum;
    } else if (warp == 1) {
        // ---- write softmax, entropy, top-3 sparse ----
        const float v = logi[lane];
        float m = v;
        #pragma unroll
        for (int o = 16; o; o >>= 1) m = fmaxf(m, __shfl_xor_sync(0xffffffffu, m, o));
        const float e = __expf(v - m);
        float ssum = e;
        #pragma unroll
        for (int o = 16; o; o >>= 1) ssum += __shfl_xor_sync(0xffffffffu, ssum, o);
        const float w = e / ssum;

        // entropy contribution (mean over B accumulated atomically)
        float ent = -w * __logf(w + 1e-10f);
        #pragma unroll
        for (int o = 16; o; o >>= 1) ent += __shfl_xor_sync(0xffffffffu, ent, o);
        if (lane == 0) atomicAdd(out + OFF_ENT, ent * (1.0f / (float)B_));

        // top-3 via iterated butterfly argmax (tie -> lowest index, matching top_k)
        float vv = w;
        float sp = 0.0f;
        float sumTop = 0.0f;
        #pragma unroll
        for (int k = 0; k < KTOP; k++) {
            float mv = vv;
            int   mi = lane;
            #pragma unroll
            for (int o = 16; o; o >>= 1) {
                const float ov = __shfl_xor_sync(0xffffffffu, mv, o);
                const int   oi = __shfl_xor_sync(0xffffffffu, mi, o);
                if (ov > mv || (ov == mv && oi < mi)) { mv = ov; mi = oi; }
            }
            sumTop += mv;
            if (lane == mi) { sp = mv; vv = -INFINITY; }
        }
        sparse[lane] = sp / (sumTop + 1e-6f);
    } else if (warp == 2) {
        // ---- write gate: sigmoid(flat . Wg + bg) ----
        float acc = 0.0f;
        #pragma unroll
        for (int i = 0; i < 4; i++) {
            const int j = lane + i * 32;
            const float f = (j < 64) ? gwr[j] : gwi[j - 64];
            acc = fmaf(f, Wg[j], acc);
        }
        #pragma unroll
        for (int o = 16; o; o >>= 1) acc += __shfl_xor_sync(0xffffffffu, acc, o);
        if (lane == 0) s_wg = 1.0f / (1.0f + __expf(-(acc + bg[0])));
    }
    __syncthreads();

    // ---- read vectors: threads 0..127 (warp0-1: read_r, warp2-3: read_i) ----
    if (t < 128) {
        const int d = t & 63;
        const float* msrc = (t < 64) ? smr : smi;
        float acc = 0.0f;
        #pragma unroll
        for (int s = 0; s < S_; s++) acc = fmaf(attn[s], msrc[s * D_ + d], acc);
        const long long off = ((t < 64) ? OFF_READ_R : OFF_READ_I) + (long long)b * D_ + d;
        out[off] = acc;
    }

    // ---- memory update + LayerNorm: 8 threads per slot row ----
    {
        const int row = t >> 3;
        const int q   = t & 7;
        const int d0  = q * 8;
        const float eff = s_wg * sparse[row];
        const float om  = 1.0f - eff;

        float v[8];
        // ----- real part -----
        float sum = 0.0f, sq = 0.0f;
        #pragma unroll
        for (int i = 0; i < 8; i++) {
            const int d = d0 + i;
            const float x = om * smr[row * D_ + d] + eff * gwr[d];
            v[i] = x; sum += x; sq = fmaf(x, x, sq);
        }
        sum += __shfl_xor_sync(0xffffffffu, sum, 4); sq += __shfl_xor_sync(0xffffffffu, sq, 4);
        sum += __shfl_xor_sync(0xffffffffu, sum, 2); sq += __shfl_xor_sync(0xffffffffu, sq, 2);
        sum += __shfl_xor_sync(0xffffffffu, sum, 1); sq += __shfl_xor_sync(0xffffffffu, sq, 1);
        float mean = sum * (1.0f / 64.0f);
        float var  = sq * (1.0f / 64.0f) - mean * mean;
        float rstd = rsqrtf(var + 1e-5f);
        {
            float o0[8];
            #pragma unroll
            for (int i = 0; i < 8; i++) {
                const int d = d0 + i;
                o0[i] = fmaf((v[i] - mean) * rstd, gr[d], br[d]);
            }
            float4* dst = (float4*)(out + OFF_NEXT_R + baseSD + row * D_ + d0);
            dst[0] = make_float4(o0[0], o0[1], o0[2], o0[3]);
            dst[1] = make_float4(o0[4], o0[5], o0[6], o0[7]);
        }
        // ----- imag part -----
        sum = 0.0f; sq = 0.0f;
        #pragma unroll
        for (int i = 0; i < 8; i++) {
            const int d = d0 + i;
            const float x = om * smi[row * D_ + d] + eff * gwi[d];
            v[i] = x; sum += x; sq = fmaf(x, x, sq);
        }
        sum += __shfl_xor_sync(0xffffffffu, sum, 4); sq += __shfl_xor_sync(0xffffffffu, sq, 4);
        sum += __shfl_xor_sync(0xffffffffu, sum, 2); sq += __shfl_xor_sync(0xffffffffu, sq, 2);
        sum += __shfl_xor_sync(0xffffffffu, sum, 1); sq += __shfl_xor_sync(0xffffffffu, sq, 1);
        mean = sum * (1.0f / 64.0f);
        var  = sq * (1.0f / 64.0f) - mean * mean;
        rstd = rsqrtf(var + 1e-5f);
        {
            float o1[8];
            #pragma unroll
            for (int i = 0; i < 8; i++) {
                const int d = d0 + i;
                o1[i] = fmaf((v[i] - mean) * rstd, gi[d], bi[d]);
            }
            float4* dst = (float4*)(out + OFF_NEXT_I + baseSD + row * D_ + d0);
            dst[0] = make_float4(o1[0], o1[1], o1[2], o1[3]);
            dst[1] = make_float4(o1[4], o1[5], o1[6], o1[7]);
        }
    }
}

extern "C" void kernel_launch(void* const* d_in, const int* in_sizes, int n_in,
                              void* d_out, int out_size)
{
    const float* gw_r    = (const float*)d_in[0];
    const float* gw_i    = (const float*)d_in[1];
    const float* mem_r   = (const float*)d_in[2];
    const float* mem_i   = (const float*)d_in[3];
    const float* Wg      = (const float*)d_in[4];
    const float* bg      = (const float*)d_in[5];
    const float* Wa      = (const float*)d_in[6];
    const float* ba      = (const float*)d_in[7];
    const float* gamma_r = (const float*)d_in[8];
    const float* beta_r  = (const float*)d_in[9];
    const float* gamma_i = (const float*)d_in[10];
    const float* beta_i  = (const float*)d_in[11];
    float* out = (float*)d_out;

    am_init_kernel<<<1, 1>>>(out);
    am_fused_kernel<<<B_, 256>>>(gw_r, gw_i, mem_r, mem_i, Wg, bg, Wa, ba,
                                 gamma_r, beta_r, gamma_i, beta_i, out);
}